// round 13
// baseline (speedup 1.0000x reference)
#include <cuda_runtime.h>

// ---------------------------------------------------------------------------
// Fused pre-MLP(tanh) -> complex FIR(32) -> post-MLP(relu), one HBM pass.
// R6b: pre-MLP replaced by a 2048-segment linear-interp LUT (built by a tiny
//      first kernel with exact tanhf), stage-C relu-MLP paired via fma.f32x2.
//      (R9 fix: removed a zero-width-space typo that broke compilation.)
// ---------------------------------------------------------------------------

#define FILTER_LEN 32
#define HALO       (FILTER_LEN - 1)          // 31
#define W_IN       262144
#define W_OUT      (W_IN - HALO)             // 262113
#define BATCH      16
#define THREADS    128
#define WARPS      4
#define T_OUT      8
#define WTILE      256                        // outputs per warp
#define TILE       (WARPS * WTILE)            // 1024 outputs per block
#define TILES_ROW  ((W_OUT + TILE - 1) / TILE)  // 256
#define PAD(i)     ((i) + ((i) >> 3))
#define SEG        324                        // float2 slots per warp segment

#define LUT_N      2048
#define LUT_SCALE  256.0f                     // index = mag * 256, range [0,8)

#define OUT_SCALE  0.17782794100389228f       // sqrt(10^(-15/10))

// LUT: entry j = (sc(j/256), sc((j+1)/256)), pair-duplicated for one LDS.64
__device__ float2 g_lut[LUT_N];

// ---- packed f32x2 helpers ----
__device__ __forceinline__ unsigned long long pk2(float lo, float hi) {
    unsigned long long r;
    asm("mov.b64 %0, {%1, %2};" : "=l"(r) : "f"(lo), "f"(hi));
    return r;
}
__device__ __forceinline__ void upk2(unsigned long long v, float& lo, float& hi) {
    asm("mov.b64 {%0, %1}, %2;" : "=f"(lo), "=f"(hi) : "l"(v));
}
__device__ __forceinline__ unsigned long long ffma2(unsigned long long a,
                                                    unsigned long long b,
                                                    unsigned long long c) {
    unsigned long long d;
    asm("fma.rn.f32x2 %0, %1, %2, %3;" : "=l"(d) : "l"(a), "l"(b), "l"(c));
    return d;
}
__device__ __forceinline__ unsigned long long lds64(const float2* p) {
    return *reinterpret_cast<const unsigned long long*>(p);
}

// ---------------------------------------------------------------------------
// Kernel 1: build the pre-MLP LUT with exact tanhf (runs in ~1 us)
// ---------------------------------------------------------------------------
__global__ void build_lut_kernel(const float* __restrict__ w1_pre,
                                 const float* __restrict__ w2_pre) {
    int j = blockIdx.x * blockDim.x + threadIdx.x;
    if (j >= LUT_N) return;
    float w1[8], w2[8];
#pragma unroll
    for (int k = 0; k < 8; k++) { w1[k] = w1_pre[k]; w2[k] = w2_pre[k]; }

    float m0 = (float)j * (1.0f / LUT_SCALE);
    float m1 = (float)(j + 1) * (1.0f / LUT_SCALE);

    float f0 = 0.0f, f1 = 0.0f, d0 = 0.0f;
#pragma unroll
    for (int k = 0; k < 8; k++) {
        f0 += w2[k] * tanhf(w1[k] * m0);
        f1 += w2[k] * tanhf(w1[k] * m1);
        d0 += w2[k] * w1[k];                 // limit of f(m)/m at m -> 0
    }
    float s0 = (j == 0) ? d0 : f0 / m0;
    float s1 = f1 / m1;
    g_lut[j] = make_float2(s0, s1);
}

// ---------------------------------------------------------------------------
// Kernel 2: main fused pipeline
// ---------------------------------------------------------------------------
__global__ void __launch_bounds__(THREADS, 6)
hammer_wiener_kernel(const float* __restrict__ x_real,
                     const float* __restrict__ x_imag,
                     const float* __restrict__ w_fir_r,
                     const float* __restrict__ w_fir_i,
                     const float* __restrict__ w1_post,
                     const float* __restrict__ b1_post,
                     const float* __restrict__ w2_post,
                     const float* __restrict__ b2_post,
                     float2* __restrict__ out) {
    __shared__ float2 s_lut[LUT_N];          // 16 KB
    __shared__ float2 s_xh[WARPS * SEG];     // per-warp packed windows
    __shared__ float2 s_wrb[FILTER_LEN];     // (wr, wr)
    __shared__ float2 s_wib[FILTER_LEN];     // (wi, wi)
    __shared__ float2 s_w1b2[8];             // (w1_post, w1_post)
    __shared__ float2 s_b1b2[8];
    __shared__ float2 s_w2b2[8];
    __shared__ float  s_b2b;

    const int tid    = threadIdx.x;
    const int lane   = tid & 31;
    const int wrp    = tid >> 5;
    const int b      = blockIdx.y;
    const int wstart = blockIdx.x * TILE + wrp * WTILE;

    // ---- params + LUT -> shared ----
    if (tid < FILTER_LEN) {
        float wr = w_fir_r[tid];
        float wi = w_fir_i[tid];
        s_wrb[tid] = make_float2(wr, wr);
        s_wib[tid] = make_float2(wi, wi);
    }
    if (tid >= 32 && tid < 40) {
        int j = tid - 32;
        float a = w1_post[j], c = b1_post[j], d = w2_post[j];
        s_w1b2[j] = make_float2(a, a);
        s_b1b2[j] = make_float2(c, c);
        s_w2b2[j] = make_float2(d, d);
    }
    if (tid == 40) s_b2b = b2_post[0];
    {
        const float4* src = reinterpret_cast<const float4*>(g_lut);
        float4*       dst = reinterpret_cast<float4*>(s_lut);
#pragma unroll
        for (int t = 0; t < (LUT_N / 2) / THREADS; t++)   // 1024 float4 total
            dst[tid + t * THREADS] = src[tid + t * THREADS];
    }
    __syncthreads();

    float2* __restrict__ seg = s_xh + wrp * SEG;

    // ---- stage A: LUT-based pre nonlinearity -> per-warp window (288) ----
    const float* __restrict__ xr_row = x_real + (size_t)b * W_IN;
    const float* __restrict__ xi_row = x_imag + (size_t)b * W_IN;

    float rv[9], iv[9];
#pragma unroll
    for (int t = 0; t < 9; t++) {
        int g = wstart + lane + 32 * t;
        bool ok = (g < W_IN);
        rv[t] = ok ? xr_row[g] : 0.0f;
        iv[t] = ok ? xi_row[g] : 0.0f;
    }
#pragma unroll
    for (int t = 0; t < 9; t++) {
        float r = rv[t], im = iv[t];
        float m2  = fmaf(r, r, im * im);
        float inv = rsqrtf(m2);
        float mag = (m2 > 0.0f) ? m2 * inv : 0.0f;
        float u   = fminf(mag * LUT_SCALE, 2047.0f);
        int   ji  = (int)u;
        float fr  = u - (float)ji;
        float2 p  = s_lut[ji];
        float sc  = fmaf(fr, p.y - p.x, p.x);
        int i = lane + 32 * t;
        seg[PAD(i)] = make_float2(sc * r, sc * im);
    }
    __syncwarp();

    // ---- stage B: 32-tap complex FIR, ring-buffer window ----
    const int base = lane * T_OUT;

    unsigned long long Wd[8];
#pragma unroll
    for (int i = 0; i < 8; i++) Wd[i] = lds64(&seg[PAD(base + i)]);

    unsigned long long acc1[T_OUT], acc2[T_OUT];
#pragma unroll
    for (int j = 0; j < T_OUT; j++) { acc1[j] = 0ULL; acc2[j] = 0ULL; }

#pragma unroll
    for (int k = 0; k < FILTER_LEN; k++) {
        unsigned long long wrb = lds64(&s_wrb[k]);
        unsigned long long wib = lds64(&s_wib[k]);
#pragma unroll
        for (int j = 0; j < T_OUT; j++) {
            unsigned long long a = Wd[(k + j) & 7];
            acc1[j] = ffma2(wrb, a, acc1[j]);
            acc2[j] = ffma2(wib, a, acc2[j]);
        }
        if (k < FILTER_LEN - 1)
            Wd[k & 7] = lds64(&seg[PAD(base + k + 8)]);
    }

    // ---- stage C: post nonlinearity (paired f32x2) + store ----
    const size_t out_base = (size_t)b * W_OUT;
    const int    n0       = wstart + base;
    const float  b2b      = s_b2b;
#pragma unroll
    for (int j = 0; j < T_OUT; j += 2) {
        float a1lo, a1hi, a2lo, a2hi;
        upk2(acc1[j], a1lo, a1hi);
        upk2(acc2[j], a2lo, a2hi);
        float zr0 = a1lo - a2hi;
        float zi0 = a1hi + a2lo;
        upk2(acc1[j + 1], a1lo, a1hi);
        upk2(acc2[j + 1], a2lo, a2hi);
        float zr1 = a1lo - a2hi;
        float zi1 = a1hi + a2lo;

        float m20  = fmaf(zr0, zr0, zi0 * zi0);
        float m21  = fmaf(zr1, zr1, zi1 * zi1);
        float inv0 = rsqrtf(m20);
        float inv1 = rsqrtf(m21);
        bool  nz0  = (m20 > 0.0f);
        bool  nz1  = (m21 > 0.0f);
        float zg0  = nz0 ? m20 * inv0 : 0.0f;
        float zg1  = nz1 ? m21 * inv1 : 0.0f;

        unsigned long long zm2 = pk2(zg0, zg1);
        unsigned long long acc = pk2(b2b, b2b);
#pragma unroll
        for (int f = 0; f < 8; f++) {
            unsigned long long g2 = ffma2(zm2, lds64(&s_w1b2[f]), lds64(&s_b1b2[f]));
            float glo, ghi;
            upk2(g2, glo, ghi);
            glo = fmaxf(glo, 0.0f);
            ghi = fmaxf(ghi, 0.0f);
            acc = ffma2(pk2(glo, ghi), lds64(&s_w2b2[f]), acc);
        }
        float zm0, zm1;
        upk2(acc, zm0, zm1);
        float sm0 = OUT_SCALE * zm0;
        float sm1 = OUT_SCALE * zm1;

        float t0 = sm0 * inv0;               // sm / |z|
        float t1 = sm1 * inv1;
        float yr0 = nz0 ? t0 * zr0 : sm0;    // cos(atan2(0,0)) = 1
        float yi0 = nz0 ? t0 * zi0 : 0.0f;
        float yr1 = nz1 ? t1 * zr1 : sm1;
        float yi1 = nz1 ? t1 * zi1 : 0.0f;

        int n = n0 + j;
        if (n < W_OUT)     out[out_base + n]     = make_float2(yr0, yi0);
        if (n + 1 < W_OUT) out[out_base + n + 1] = make_float2(yr1, yi1);
    }
}

extern "C" void kernel_launch(void* const* d_in, const int* in_sizes, int n_in,
                              void* d_out, int out_size) {
    (void)in_sizes; (void)n_in; (void)out_size;
    const float* x_real   = (const float*)d_in[0];
    const float* x_imag   = (const float*)d_in[1];
    const float* w1_pre   = (const float*)d_in[2];
    const float* w2_pre   = (const float*)d_in[3];
    const float* w_fir_r  = (const float*)d_in[4];
    const float* w_fir_i  = (const float*)d_in[5];
    const float* w1_post  = (const float*)d_in[6];
    const float* b1_post  = (const float*)d_in[7];
    const float* w2_post  = (const float*)d_in[8];
    const float* b2_post  = (const float*)d_in[9];

    build_lut_kernel<<<LUT_N / 256, 256>>>(w1_pre, w2_pre);

    dim3 grid(TILES_ROW, BATCH);
    hammer_wiener_kernel<<<grid, THREADS>>>(
        x_real, x_imag, w_fir_r, w_fir_i,
        w1_post, b1_post, w2_post, b2_post, (float2*)d_out);
}